// round 11
// baseline (speedup 1.0000x reference)
#include <cuda_runtime.h>
#include <cuda_bf16.h>
#include <cstdint>

// ---------------------------------------------------------------------------
// DownSample_7945689498135 — fused im2col + bf16-split HMMA GEMM, 512-thread CTA
// (tcgen05 unavailable: harness compiles via compute_103, no 'a' features)
// Inputs: 0 sparse_fea[64,256,64] 1 dense_fea[64,128,4096] 2 stk_coor[64,64,32]
//         3 conv_w[256,128,1,3] 4 conv_b (cancels in BN) 5 bn_gamma 6 bn_beta
// Output fp32 concat: sparse_out[64,256,32] | dense_out[64,256,1024] | coor[64,32,32]
// ---------------------------------------------------------------------------

#define BSZ    64
#define SPEMB  256
#define DIN    128
#define DOUT   256
#define NSTK   64
#define NHALF  32
#define QOUT   32
#define KTOT   384

#define SP_OFF 0
#define DN_OFF (BSZ*SPEMB*NHALF)                 // 524288
#define CO_OFF (DN_OFF + BSZ*DOUT*NHALF*QOUT)    // 17301504

__device__ __nv_bfloat16 g_Wh[DOUT*KTOT];   // k = tap*128 + i (tap-major)
__device__ __nv_bfloat16 g_Wl[DOUT*KTOT];
__device__ float g_y[BSZ*DOUT*NHALF*QOUT];
__device__ float g_sum[DOUT], g_sumsq[DOUT], g_scale[DOUT], g_shift[DOUT];
__device__ int   g_fps[BSZ*NHALF];

#define SWZ(x) ((x) ^ (((x) >> 3) & 0x70))

// gemm smem layout (bytes, dynamic) — same as R10
#define AH_OFF   0
#define AL_OFF   66560
#define B_H_OFF  133120     // 256 oc x 64k bf16 = 32KB, 128B rows, SWZ
#define B_L_OFF  165888
#define RAW_OFF  133120     // prologue staging: 2 strokes x (128 i x 272B)
#define STG_OFF  0          // epilogue: 256 x 132 fp32 = 135168
#define SSUM_OFF 135168
#define SSQ_OFF  136192
#define DYN_SMEM 202752

__device__ __forceinline__ uint32_t smem_u32(const void* p) {
    uint32_t a;
    asm("{ .reg .u64 t; cvta.to.shared.u64 t, %1; cvt.u32.u64 %0, t; }" : "=r"(a) : "l"(p));
    return a;
}
__device__ __forceinline__ void cp16(uint32_t dst, const void* src) {
    asm volatile("cp.async.cg.shared.global [%0], [%1], 16;" :: "r"(dst), "l"(src));
}
#define CP_COMMIT() asm volatile("cp.async.commit_group;" ::: "memory")
#define CP_WAIT0()  asm volatile("cp.async.wait_group 0;" ::: "memory")

__device__ __forceinline__ void ldm4(uint32_t addr, uint32_t& r0, uint32_t& r1,
                                     uint32_t& r2, uint32_t& r3) {
    asm volatile("ldmatrix.sync.aligned.m8n8.x4.shared.b16 {%0,%1,%2,%3}, [%4];"
                 : "=r"(r0), "=r"(r1), "=r"(r2), "=r"(r3) : "r"(addr));
}
__device__ __forceinline__ void mma16816(float* c, const uint32_t* a, uint32_t b0, uint32_t b1) {
    asm volatile("mma.sync.aligned.m16n8k16.row.col.f32.bf16.bf16.f32 "
                 "{%0,%1,%2,%3}, {%4,%5,%6,%7}, {%8,%9}, {%0,%1,%2,%3};"
                 : "+f"(c[0]), "+f"(c[1]), "+f"(c[2]), "+f"(c[3])
                 : "r"(a[0]), "r"(a[1]), "r"(a[2]), "r"(a[3]), "r"(b0), "r"(b1));
}

// ---------------------------------------------------------------------------
__global__ void init_w(const float* __restrict__ w) {
    int idx = blockIdx.x * 256 + threadIdx.x;       // 98304
    int oc = idx / 384, rem = idx - oc * 384;
    int tap = rem >> 7, i = rem & 127;
    float v = w[oc * 384 + i * 3 + tap];
    __nv_bfloat16 h = __float2bfloat16_rn(v);
    g_Wh[idx] = h;
    g_Wl[idx] = __float2bfloat16_rn(v - __bfloat162float(h));
    if (idx < DOUT) { g_sum[idx] = 0.f; g_sumsq[idx] = 0.f; }
}

// ---------------------------------------------------------------------------
__global__ void fps_kernel(const float* __restrict__ coor, float* __restrict__ out3) {
    __shared__ float sh[NSTK * 33];
    __shared__ float sd[NSTK];
    __shared__ int   si[NSTK];
    __shared__ int   sel[NHALF];
    int b = blockIdx.x, t = threadIdx.x;
    const float* src = coor + b * NSTK * 32;
#pragma unroll
    for (int r = 0; r < 32; r++) {
        int l = r * 64 + t;
        sh[(l >> 5) * 33 + (l & 31)] = src[l];
    }
    __syncthreads();
    float mind = 1e10f;
    int far = 0;
    const float* mine = sh + t * 33;
    for (int i = 0; i < NHALF; i++) {
        if (t == 0) { sel[i] = far; g_fps[b * NHALF + i] = far; }
        const float* cent = sh + far * 33;
        float d = 0.f;
#pragma unroll
        for (int c = 0; c < 32; c++) { float df = mine[c] - cent[c]; d = fmaf(df, df, d); }
        mind = fminf(mind, d);
        sd[t] = mind; si[t] = t;
        __syncthreads();
        for (int off = 32; off; off >>= 1) {
            if (t < off) {
                float d2 = sd[t + off]; int i2 = si[t + off];
                if (d2 > sd[t] || (d2 == sd[t] && i2 < si[t])) { sd[t] = d2; si[t] = i2; }
            }
            __syncthreads();
        }
        far = si[0];
        __syncthreads();
    }
#pragma unroll
    for (int r = 0; r < 16; r++) {
        int l = r * 64 + t;
        out3[b * 1024 + l] = sh[sel[l >> 5] * 33 + (l & 31)];
    }
}

// ---------------------------------------------------------------------------
__global__ void gather_sparse(const float* __restrict__ sp, float* __restrict__ outp) {
    int idx = blockIdx.x * 256 + threadIdx.x;
    int b = idx >> 13;
    int r = idx & 8191;
    int c = r >> 5, jj = r & 31;
    outp[idx] = sp[b * (SPEMB * NSTK) + c * NSTK + g_fps[b * NHALF + jj]];
}

// ---------------------------------------------------------------------------
// Fused GEMM: one CTA = 4 strokes (m=128 positions) x all 256 oc, 512 threads.
// Warp grid 4(m) x 4(n): warp tile m32 x n64, acc[2][8][4] = 64 regs/thread.
// ---------------------------------------------------------------------------
__global__ void __launch_bounds__(512, 1) gemm_kernel(const float* __restrict__ dense) {
    extern __shared__ __align__(128) char smem[];
    uint32_t sb = smem_u32(smem);
    int t = threadIdx.x, wid = t >> 5, lane = t & 31;
    int mt = blockIdx.x;               // 0..511
    int b = mt >> 3;
    int wm = wid & 3, wn = wid >> 2;   // warp tile: m32 x n64

    // ---- prologue: load + convert 4 strokes (2 at a time) ----
    for (int p = 0; p < 2; p++) {
        int s0 = g_fps[mt * 4 + p * 2];
        int s1 = g_fps[mt * 4 + p * 2 + 1];
#pragma unroll
        for (int rep = 0; rep < 8; rep++) {
            int id = rep * 512 + t;           // 0..4095 (2 strokes x 128 i x 16 x 16B)
            int stL = id >> 11, rid = id & 2047;
            int i = rid >> 4, p4 = rid & 15;
            int s = stL ? s1 : s0;
            cp16(sb + RAW_OFF + stL * 34816 + i * 272 + p4 * 16,
                 dense + (size_t)b * 524288 + (size_t)i * 4096 + s * 64 + p4 * 4);
        }
        CP_COMMIT();
        CP_WAIT0();
        __syncthreads();
#pragma unroll 4
        for (int iter = 0; iter < 32; iter++) {
            int e = iter * 512 + t;           // 0..16383
            int stL = e >> 13, rem = e & 8191;
            int i = rem >> 6, pt = rem & 63;
            float v = *reinterpret_cast<const float*>(
                smem + RAW_OFF + stL * 34816 + i * 272 + pt * 4);
            int st = p * 2 + stL;
            int r = pt + 1;
            int sw = r * 256 + ((((i >> 3) ^ ((r >> 1) & 7)) << 4) | ((i & 7) * 2));
            __nv_bfloat16 h = __float2bfloat16_rn(v);
            *reinterpret_cast<__nv_bfloat16*>(smem + AH_OFF + st * 16640 + sw) = h;
            *reinterpret_cast<__nv_bfloat16*>(smem + AL_OFF + st * 16640 + sw) =
                __float2bfloat16_rn(v - __bfloat162float(h));
        }
        __syncthreads();                      // raw reuse safe
    }
    // zero pad row r=0 (pt = -1) of each stroke; r=0 swizzle is identity
    if (t < 256) {
        int st = t >> 6, i4 = t & 63;
        *reinterpret_cast<uint32_t*>(smem + AH_OFF + st * 16640 + i4 * 4) = 0;
        *reinterpret_cast<uint32_t*>(smem + AL_OFF + st * 16640 + i4 * 4) = 0;
    }

    float acc[2][8][4];
#pragma unroll
    for (int i = 0; i < 2; i++)
#pragma unroll
        for (int j = 0; j < 8; j++)
#pragma unroll
            for (int k = 0; k < 4; k++) acc[i][j][k] = 0.f;

    auto ldB = [&](int kc, uint32_t off, const __nv_bfloat16* W) {
#pragma unroll
        for (int rep = 0; rep < 4; rep++) {
            int id = rep * 512 + t;           // 2048: 256 rows x 8 x 16B
            int row = id >> 3, c = id & 7;
            cp16(sb + off + SWZ(row * 128 + c * 16),
                 W + (size_t)row * 384 + kc * 64 + c * 8);
        }
    };

    auto pass = [&](uint32_t Abase, uint32_t Bbase, int tap, int ihalf) {
        int lr = lane & 15, lh = lane >> 4;
#pragma unroll
        for (int kk = 0; kk < 4; kk++) {
            uint32_t bf[4][4];
#pragma unroll
            for (int nq = 0; nq < 4; nq++)
                ldm4(sb + Bbase + SWZ((wn * 64 + nq * 16 + lr) * 128 + kk * 32 + lh * 16),
                     bf[nq][0], bf[nq][1], bf[nq][2], bf[nq][3]);
#pragma unroll
            for (int mm = 0; mm < 2; mm++) {
                int qp = wm * 32 + mm * 16 + lr;
                int st = qp >> 5, q = qp & 31;
                int r = 2 * q + tap;
                int c16 = ihalf * 8 + kk * 2 + lh;
                uint32_t a[4];
                ldm4(sb + Abase + st * 16640 + r * 256 +
                         ((c16 ^ ((r >> 1) & 7)) << 4),
                     a[0], a[1], a[2], a[3]);
#pragma unroll
                for (int nq = 0; nq < 4; nq++) {
                    mma16816(acc[mm][nq * 2],     a, bf[nq][0], bf[nq][2]);
                    mma16816(acc[mm][nq * 2 + 1], a, bf[nq][1], bf[nq][3]);
                }
            }
        }
    };

    ldB(0, B_H_OFF, g_Wh);
    CP_COMMIT();

    for (int kc = 0; kc < 6; kc++) {
        int tap = kc >> 1, ihalf = kc & 1;
        CP_WAIT0();                            // Bh(kc) arrived
        __syncthreads();                       // visible; prev Bl consumers done
        ldB(kc, B_L_OFF, g_Wl);
        CP_COMMIT();
        pass(AH_OFF, B_H_OFF, tap, ihalf);     // xh * wh
        pass(AL_OFF, B_H_OFF, tap, ihalf);     // xl * wh
        CP_WAIT0();                            // Bl(kc) arrived
        __syncthreads();                       // visible; Bh free
        if (kc < 5) { ldB(kc + 1, B_H_OFF, g_Wh); CP_COMMIT(); }
        pass(AH_OFF, B_L_OFF, tap, ihalf);     // xh * wl
    }
    __syncthreads();                           // A region free for staging

    // ---- epilogue: BN partials + transpose -> g_y ----
    float* so   = reinterpret_cast<float*>(smem + STG_OFF);   // [256 oc][132]
    float* ssum = reinterpret_cast<float*>(smem + SSUM_OFF);
    float* ssq  = reinterpret_cast<float*>(smem + SSQ_OFF);
    if (t < 256) { ssum[t] = 0.f; ssq[t] = 0.f; }
    __syncthreads();

    {
        int r0 = wm * 32 + (lane >> 2);
#pragma unroll
        for (int nn = 0; nn < 8; nn++) {
            int n = wn * 64 + nn * 8 + (lane & 3) * 2;
            float s0 = 0.f, q0 = 0.f, s1 = 0.f, q1 = 0.f;
#pragma unroll
            for (int mm = 0; mm < 2; mm++) {
                float v0 = acc[mm][nn][0], v1 = acc[mm][nn][1];
                float v2 = acc[mm][nn][2], v3 = acc[mm][nn][3];
                s0 += v0 + v2; q0 += v0 * v0 + v2 * v2;
                s1 += v1 + v3; q1 += v1 * v1 + v3 * v3;
                int rm = r0 + mm * 16;
                so[n * 132 + rm]           = v0;
                so[(n + 1) * 132 + rm]     = v1;
                so[n * 132 + rm + 8]       = v2;
                so[(n + 1) * 132 + rm + 8] = v3;
            }
            atomicAdd(&ssum[n], s0);     atomicAdd(&ssq[n], q0);
            atomicAdd(&ssum[n + 1], s1); atomicAdd(&ssq[n + 1], q1);
        }
    }
    __syncthreads();

    if (t < 256) {
        atomicAdd(&g_sum[t], ssum[t]);
        atomicAdd(&g_sumsq[t], ssq[t]);
    }

    int plb = (mt & 7) * 128;
#pragma unroll
    for (int it = 0; it < 16; it++) {
        int idx4 = it * 512 + t;               // 8192 float4
        int n = idx4 >> 5, m4 = idx4 & 31;
        float4 v = *reinterpret_cast<const float4*>(so + n * 132 + m4 * 4);
        *reinterpret_cast<float4*>(g_y + (size_t)b * 262144 +
            (size_t)n * 1024 + plb + m4 * 4) = v;
    }
}

// ---------------------------------------------------------------------------
__global__ void bn_finalize(const float* __restrict__ gamma, const float* __restrict__ beta) {
    int t = threadIdx.x;
    const float inv_n = 1.f / 65536.f;
    float m = g_sum[t] * inv_n;
    float v = g_sumsq[t] * inv_n - m * m;
    float inv = rsqrtf(v + 1e-5f);
    float g = gamma[t] * inv;
    g_scale[t] = g;
    g_shift[t] = beta[t] - m * g;
}

__device__ __forceinline__ float gelu_t(float x) {
    float x3 = x * x * x;
    float u = 0.7978845608028654f * fmaf(0.044715f, x3, x);
    return 0.5f * x * (1.f + tanhf(u));
}

__global__ void bn_act_kernel(float* __restrict__ outp) {
    int idx4 = blockIdx.x * 256 + threadIdx.x;
    const float4* gy4 = reinterpret_cast<const float4*>(g_y);
    float4 v = gy4[idx4];
    int o = (idx4 >> 8) & 255;
    float sc = g_scale[o], sh = g_shift[o];
    v.x = gelu_t(fmaf(v.x, sc, sh));
    v.y = gelu_t(fmaf(v.y, sc, sh));
    v.z = gelu_t(fmaf(v.z, sc, sh));
    v.w = gelu_t(fmaf(v.w, sc, sh));
    reinterpret_cast<float4*>(outp)[idx4] = v;
}

// ---------------------------------------------------------------------------
extern "C" void kernel_launch(void* const* d_in, const int* in_sizes, int n_in,
                              void* d_out, int out_size) {
    const float* sparse = (const float*)d_in[0];
    const float* dense  = (const float*)d_in[1];
    const float* coor   = (const float*)d_in[2];
    const float* convw  = (const float*)d_in[3];
    const float* gamma  = (const float*)d_in[5];
    const float* beta   = (const float*)d_in[6];
    float* out = (float*)d_out;

    cudaFuncSetAttribute(gemm_kernel, cudaFuncAttributeMaxDynamicSharedMemorySize, DYN_SMEM);

    init_w<<<384, 256>>>(convw);
    fps_kernel<<<BSZ, 64>>>(coor, out + CO_OFF);
    gather_sparse<<<2048, 256>>>(sparse, out + SP_OFF);
    gemm_kernel<<<512, 512, DYN_SMEM>>>(dense);
    bn_finalize<<<1, DOUT>>>(gamma, beta);
    bn_act_kernel<<<16384, 256>>>(out + DN_OFF);
}

// round 13
// speedup vs baseline: 1.2156x; 1.2156x over previous
#include <cuda_runtime.h>
#include <cuda_bf16.h>
#include <cstdint>

// ---------------------------------------------------------------------------
// DownSample_7945689498135 — fused im2col + bf16-split HMMA GEMM
// CTA = 2 strokes (m=64) x 128 oc, 256 threads, 99KB smem -> 2 CTA/SM.
// (tcgen05 unavailable: harness compiles via compute_103, no 'a' features)
// Inputs: 0 sparse_fea[64,256,64] 1 dense_fea[64,128,4096] 2 stk_coor[64,64,32]
//         3 conv_w[256,128,1,3] 4 conv_b (cancels in BN) 5 bn_gamma 6 bn_beta
// Output fp32 concat: sparse_out[64,256,32] | dense_out[64,256,1024] | coor[64,32,32]
// ---------------------------------------------------------------------------

#define BSZ    64
#define SPEMB  256
#define DIN    128
#define DOUT   256
#define NSTK   64
#define NHALF  32
#define QOUT   32
#define KTOT   384

#define SP_OFF 0
#define DN_OFF (BSZ*SPEMB*NHALF)                 // 524288
#define CO_OFF (DN_OFF + BSZ*DOUT*NHALF*QOUT)    // 17301504

__device__ __nv_bfloat16 g_Wh[DOUT*KTOT];   // k = tap*128 + i (tap-major)
__device__ __nv_bfloat16 g_Wl[DOUT*KTOT];
__device__ float g_y[BSZ*DOUT*NHALF*QOUT];
__device__ float g_sum[DOUT], g_sumsq[DOUT], g_scale[DOUT], g_shift[DOUT];
__device__ int   g_fps[BSZ*NHALF];

#define SWZ(x) ((x) ^ (((x) >> 3) & 0x70))

// gemm smem layout (bytes, dynamic):
// A conv tiles: [h|l][stroke 0..1][row r=pt+1 in 0..64][i 0..127] bf16
//   row stride 256B, stroke stride 65*256=16640, XOR swizzle c16^((r>>1)&7)
#define AH_OFF   0          // 33280
#define AL_OFF   33280      // -> 66560
#define B_H_OFF  66560      // 128 oc x 64k bf16 = 16KB
#define B_L_OFF  82944      // 16KB -> 99328
#define RAW_OFF  66560      // staging: 1 stroke x 128 i x 256B = 32KB (reuses B)
#define STG_OFF  0          // epilogue: 128 oc x 68 fp32 = 34816
#define SSUM_OFF 34816
#define SSQ_OFF  35328
#define DYN_SMEM 99328

__device__ __forceinline__ uint32_t smem_u32(const void* p) {
    uint32_t a;
    asm("{ .reg .u64 t; cvta.to.shared.u64 t, %1; cvt.u32.u64 %0, t; }" : "=r"(a) : "l"(p));
    return a;
}
__device__ __forceinline__ void cp16(uint32_t dst, const void* src) {
    asm volatile("cp.async.cg.shared.global [%0], [%1], 16;" :: "r"(dst), "l"(src));
}
#define CP_COMMIT() asm volatile("cp.async.commit_group;" ::: "memory")
#define CP_WAIT0()  asm volatile("cp.async.wait_group 0;" ::: "memory")

__device__ __forceinline__ void ldm4(uint32_t addr, uint32_t& r0, uint32_t& r1,
                                     uint32_t& r2, uint32_t& r3) {
    asm volatile("ldmatrix.sync.aligned.m8n8.x4.shared.b16 {%0,%1,%2,%3}, [%4];"
                 : "=r"(r0), "=r"(r1), "=r"(r2), "=r"(r3) : "r"(addr));
}
__device__ __forceinline__ void mma16816(float* c, const uint32_t* a, uint32_t b0, uint32_t b1) {
    asm volatile("mma.sync.aligned.m16n8k16.row.col.f32.bf16.bf16.f32 "
                 "{%0,%1,%2,%3}, {%4,%5,%6,%7}, {%8,%9}, {%0,%1,%2,%3};"
                 : "+f"(c[0]), "+f"(c[1]), "+f"(c[2]), "+f"(c[3])
                 : "r"(a[0]), "r"(a[1]), "r"(a[2]), "r"(a[3]), "r"(b0), "r"(b1));
}

// ---------------------------------------------------------------------------
__global__ void init_w(const float* __restrict__ w) {
    int idx = blockIdx.x * 256 + threadIdx.x;       // 98304
    int oc = idx / 384, rem = idx - oc * 384;
    int tap = rem >> 7, i = rem & 127;
    float v = w[oc * 384 + i * 3 + tap];
    __nv_bfloat16 h = __float2bfloat16_rn(v);
    g_Wh[idx] = h;
    g_Wl[idx] = __float2bfloat16_rn(v - __bfloat162float(h));
    if (idx < DOUT) { g_sum[idx] = 0.f; g_sumsq[idx] = 0.f; }
}

// ---------------------------------------------------------------------------
__global__ void fps_kernel(const float* __restrict__ coor, float* __restrict__ out3) {
    __shared__ float sh[NSTK * 33];
    __shared__ float sd[NSTK];
    __shared__ int   si[NSTK];
    __shared__ int   sel[NHALF];
    int b = blockIdx.x, t = threadIdx.x;
    const float* src = coor + b * NSTK * 32;
#pragma unroll
    for (int r = 0; r < 32; r++) {
        int l = r * 64 + t;
        sh[(l >> 5) * 33 + (l & 31)] = src[l];
    }
    __syncthreads();
    float mind = 1e10f;
    int far = 0;
    const float* mine = sh + t * 33;
    for (int i = 0; i < NHALF; i++) {
        if (t == 0) { sel[i] = far; g_fps[b * NHALF + i] = far; }
        const float* cent = sh + far * 33;
        float d = 0.f;
#pragma unroll
        for (int c = 0; c < 32; c++) { float df = mine[c] - cent[c]; d = fmaf(df, df, d); }
        mind = fminf(mind, d);
        sd[t] = mind; si[t] = t;
        __syncthreads();
        for (int off = 32; off; off >>= 1) {
            if (t < off) {
                float d2 = sd[t + off]; int i2 = si[t + off];
                if (d2 > sd[t] || (d2 == sd[t] && i2 < si[t])) { sd[t] = d2; si[t] = i2; }
            }
            __syncthreads();
        }
        far = si[0];
        __syncthreads();
    }
#pragma unroll
    for (int r = 0; r < 16; r++) {
        int l = r * 64 + t;
        out3[b * 1024 + l] = sh[sel[l >> 5] * 33 + (l & 31)];
    }
}

// ---------------------------------------------------------------------------
__global__ void gather_sparse(const float* __restrict__ sp, float* __restrict__ outp) {
    int idx = blockIdx.x * 256 + threadIdx.x;
    int b = idx >> 13;
    int r = idx & 8191;
    int c = r >> 5, jj = r & 31;
    outp[idx] = sp[b * (SPEMB * NSTK) + c * NSTK + g_fps[b * NHALF + jj]];
}

// ---------------------------------------------------------------------------
// Fused GEMM: blockIdx = (m-tile of 2 strokes) x (oc half).
// Warp grid 2(m) x 4(n): warp tile m32 x n32, acc[2][4][4] = 32 regs/thread.
// ---------------------------------------------------------------------------
__global__ void __launch_bounds__(256, 2) gemm_kernel(const float* __restrict__ dense) {
    extern __shared__ __align__(128) char smem[];
    uint32_t sb = smem_u32(smem);
    int t = threadIdx.x, wid = t >> 5, lane = t & 31;
    int nt = blockIdx.x & 1, mt2 = blockIdx.x >> 1;   // mt2: 0..1023
    int b = mt2 >> 4, pair = mt2 & 15;
    int ocb = nt * 128;
    int wm = wid & 1, wn = wid >> 1;   // warp tile: m32 x n32

    // ---- prologue: load + convert 2 strokes (one at a time via RAW staging) ----
    for (int st = 0; st < 2; st++) {
        int s = g_fps[b * NHALF + pair * 2 + st];
#pragma unroll
        for (int rep = 0; rep < 8; rep++) {
            int id = rep * 256 + t;           // 0..2047: 128 i x 16 x 16B
            int i = id >> 4, p4 = id & 15;
            cp16(sb + RAW_OFF + i * 256 + p4 * 16,
                 dense + (size_t)b * 524288 + (size_t)i * 4096 + s * 64 + p4 * 4);
        }
        CP_COMMIT();
        CP_WAIT0();
        __syncthreads();
        const float* raw = reinterpret_cast<const float*>(smem + RAW_OFF);
#pragma unroll 4
        for (int iter = 0; iter < 32; iter++) {
            int e = iter * 256 + t;           // 0..8191
            int i = e >> 6, pt = e & 63;
            float v = raw[i * 64 + pt];
            int r = pt + 1;
            int sw = r * 256 + ((((i >> 3) ^ ((r >> 1) & 7)) << 4) | ((i & 7) * 2));
            __nv_bfloat16 h = __float2bfloat16_rn(v);
            *reinterpret_cast<__nv_bfloat16*>(smem + AH_OFF + st * 16640 + sw) = h;
            *reinterpret_cast<__nv_bfloat16*>(smem + AL_OFF + st * 16640 + sw) =
                __float2bfloat16_rn(v - __bfloat162float(h));
        }
        __syncthreads();                      // raw region reuse safe
    }
    // zero pad row r=0 (pt = -1) of each stroke; r=0 swizzle is identity
    if (t < 128) {
        int st = t >> 6, i4 = t & 63;
        *reinterpret_cast<uint32_t*>(smem + AH_OFF + st * 16640 + i4 * 4) = 0;
        *reinterpret_cast<uint32_t*>(smem + AL_OFF + st * 16640 + i4 * 4) = 0;
    }

    float acc[2][4][4];
#pragma unroll
    for (int i = 0; i < 2; i++)
#pragma unroll
        for (int j = 0; j < 4; j++)
#pragma unroll
            for (int k = 0; k < 4; k++) acc[i][j][k] = 0.f;

    auto ldB = [&](int kc, uint32_t off, const __nv_bfloat16* W) {
#pragma unroll
        for (int rep = 0; rep < 4; rep++) {
            int id = rep * 256 + t;           // 1024: 128 rows x 8 x 16B
            int row = id >> 3, c = id & 7;
            cp16(sb + off + SWZ(row * 128 + c * 16),
                 W + (size_t)(ocb + row) * 384 + kc * 64 + c * 8);
        }
    };

    auto pass = [&](uint32_t Abase, uint32_t Bbase, int tap, int ihalf) {
        int lr = lane & 15, lh = lane >> 4;
#pragma unroll
        for (int kk = 0; kk < 4; kk++) {
            uint32_t bf[2][4];
#pragma unroll
            for (int nq = 0; nq < 2; nq++)
                ldm4(sb + Bbase + SWZ((wn * 32 + nq * 16 + lr) * 128 + kk * 32 + lh * 16),
                     bf[nq][0], bf[nq][1], bf[nq][2], bf[nq][3]);
#pragma unroll
            for (int mm = 0; mm < 2; mm++) {
                int qp = wm * 32 + mm * 16 + lr;
                int st = qp >> 5, q = qp & 31;
                int r = 2 * q + tap;
                int c16 = ihalf * 8 + kk * 2 + lh;
                uint32_t a[4];
                ldm4(sb + Abase + st * 16640 + r * 256 +
                         ((c16 ^ ((r >> 1) & 7)) << 4),
                     a[0], a[1], a[2], a[3]);
#pragma unroll
                for (int nq = 0; nq < 2; nq++) {
                    mma16816(acc[mm][nq * 2],     a, bf[nq][0], bf[nq][2]);
                    mma16816(acc[mm][nq * 2 + 1], a, bf[nq][1], bf[nq][3]);
                }
            }
        }
    };

    ldB(0, B_H_OFF, g_Wh);
    CP_COMMIT();

    for (int kc = 0; kc < 6; kc++) {
        int tap = kc >> 1, ihalf = kc & 1;
        CP_WAIT0();                            // Bh(kc) arrived
        __syncthreads();                       // visible; prev Bl consumers done
        ldB(kc, B_L_OFF, g_Wl);
        CP_COMMIT();
        pass(AH_OFF, B_H_OFF, tap, ihalf);     // xh * wh
        pass(AL_OFF, B_H_OFF, tap, ihalf);     // xl * wh
        CP_WAIT0();                            // Bl(kc) arrived
        __syncthreads();                       // visible; Bh free
        if (kc < 5) { ldB(kc + 1, B_H_OFF, g_Wh); CP_COMMIT(); }
        pass(AH_OFF, B_L_OFF, tap, ihalf);     // xh * wl
    }
    __syncthreads();                           // A region free for staging

    // ---- epilogue: BN partials + transpose -> g_y ----
    float* so   = reinterpret_cast<float*>(smem + STG_OFF);   // [128 oc][68]
    float* ssum = reinterpret_cast<float*>(smem + SSUM_OFF);
    float* ssq  = reinterpret_cast<float*>(smem + SSQ_OFF);
    if (t < 128) { ssum[t] = 0.f; ssq[t] = 0.f; }
    __syncthreads();

    {
        int r0 = wm * 32 + (lane >> 2);
#pragma unroll
        for (int nn = 0; nn < 4; nn++) {
            int n = wn * 32 + nn * 8 + (lane & 3) * 2;
            float s0 = 0.f, q0 = 0.f, s1 = 0.f, q1 = 0.f;
#pragma unroll
            for (int mm = 0; mm < 2; mm++) {
                float v0 = acc[mm][nn][0], v1 = acc[mm][nn][1];
                float v2 = acc[mm][nn][2], v3 = acc[mm][nn][3];
                s0 += v0 + v2; q0 += v0 * v0 + v2 * v2;
                s1 += v1 + v3; q1 += v1 * v1 + v3 * v3;
                int rm = r0 + mm * 16;
                so[n * 68 + rm]           = v0;
                so[(n + 1) * 68 + rm]     = v1;
                so[n * 68 + rm + 8]       = v2;
                so[(n + 1) * 68 + rm + 8] = v3;
            }
            atomicAdd(&ssum[n], s0);     atomicAdd(&ssq[n], q0);
            atomicAdd(&ssum[n + 1], s1); atomicAdd(&ssq[n + 1], q1);
        }
    }
    __syncthreads();

    if (t < 128) {
        atomicAdd(&g_sum[ocb + t], ssum[t]);
        atomicAdd(&g_sumsq[ocb + t], ssq[t]);
    }

    // store: 128 oc x 64 pos = 2048 float4
#pragma unroll
    for (int it = 0; it < 8; it++) {
        int idx4 = it * 256 + t;
        int n = idx4 >> 4, m4 = idx4 & 15;
        float4 v = *reinterpret_cast<const float4*>(so + n * 68 + m4 * 4);
        *reinterpret_cast<float4*>(g_y + (size_t)b * 262144 +
            (size_t)(ocb + n) * 1024 + pair * 64 + m4 * 4) = v;
    }
}

// ---------------------------------------------------------------------------
__global__ void bn_finalize(const float* __restrict__ gamma, const float* __restrict__ beta) {
    int t = threadIdx.x;
    const float inv_n = 1.f / 65536.f;
    float m = g_sum[t] * inv_n;
    float v = g_sumsq[t] * inv_n - m * m;
    float inv = rsqrtf(v + 1e-5f);
    float g = gamma[t] * inv;
    g_scale[t] = g;
    g_shift[t] = beta[t] - m * g;
}

__device__ __forceinline__ float gelu_t(float x) {
    float x3 = x * x * x;
    float u = 0.7978845608028654f * fmaf(0.044715f, x3, x);
    return 0.5f * x * (1.f + tanhf(u));
}

__global__ void bn_act_kernel(float* __restrict__ outp) {
    int idx4 = blockIdx.x * 256 + threadIdx.x;
    const float4* gy4 = reinterpret_cast<const float4*>(g_y);
    float4 v = gy4[idx4];
    int o = (idx4 >> 8) & 255;
    float sc = g_scale[o], sh = g_shift[o];
    v.x = gelu_t(fmaf(v.x, sc, sh));
    v.y = gelu_t(fmaf(v.y, sc, sh));
    v.z = gelu_t(fmaf(v.z, sc, sh));
    v.w = gelu_t(fmaf(v.w, sc, sh));
    reinterpret_cast<float4*>(outp)[idx4] = v;
}

// ---------------------------------------------------------------------------
extern "C" void kernel_launch(void* const* d_in, const int* in_sizes, int n_in,
                              void* d_out, int out_size) {
    const float* sparse = (const float*)d_in[0];
    const float* dense  = (const float*)d_in[1];
    const float* coor   = (const float*)d_in[2];
    const float* convw  = (const float*)d_in[3];
    const float* gamma  = (const float*)d_in[5];
    const float* beta   = (const float*)d_in[6];
    float* out = (float*)d_out;

    cudaFuncSetAttribute(gemm_kernel, cudaFuncAttributeMaxDynamicSharedMemorySize, DYN_SMEM);

    init_w<<<384, 256>>>(convw);
    fps_kernel<<<BSZ, 64>>>(coor, out + CO_OFF);
    gather_sparse<<<2048, 256>>>(sparse, out + SP_OFF);
    gemm_kernel<<<2048, 256, DYN_SMEM>>>(dense);
    bn_finalize<<<1, DOUT>>>(gamma, beta);
    bn_act_kernel<<<16384, 256>>>(out + DN_OFF);
}